// round 9
// baseline (speedup 1.0000x reference)
#include <cuda_runtime.h>
#include <mma.h>
#include <math.h>
#include <stdint.h>

using namespace nvcuda;

// Problem constants
#define BATCH 2
#define SEQ 2048
#define DIM 768
#define NHEAD 12
#define HDIM 64
#define QKV_DIM (3 * DIM)     // 2304
#define M_TOTAL (BATCH * SEQ) // 4096
#define SCALE 0.125f          // 64^-0.5

// Scratch (device globals; no allocations allowed)
__device__ float g_q[BATCH * NHEAD * SEQ * HDIM];
__device__ float g_k[BATCH * NHEAD * SEQ * HDIM];
__device__ float g_v[BATCH * NHEAD * SEQ * HDIM];
__device__ float g_x[M_TOTAL * DIM];
__device__ float g_a[M_TOTAL * DIM];     // tf32-truncated inputs
__device__ float g_wq[QKV_DIM * DIM];    // tf32-truncated w_qkv
__device__ float g_wf[DIM * DIM];        // tf32-truncated w_fc
__device__ int   g_idx[BATCH * SEQ];
__device__ int   g_cnt[BATCH];

typedef wmma::fragment<wmma::matrix_a, 16, 16, 8, wmma::precision::tf32, wmma::row_major> AFrag;
typedef wmma::fragment<wmma::matrix_b, 16, 16, 8, wmma::precision::tf32, wmma::col_major> BFragCol;
typedef wmma::fragment<wmma::matrix_b, 16, 16, 8, wmma::precision::tf32, wmma::row_major> BFragRow;
typedef wmma::fragment<wmma::accumulator, 16, 16, 8, float> CFrag;

__device__ __forceinline__ float4 tf32x4(float4 v) {
    v.x = wmma::__float_to_tf32(v.x);
    v.y = wmma::__float_to_tf32(v.y);
    v.z = wmma::__float_to_tf32(v.z);
    v.w = wmma::__float_to_tf32(v.w);
    return v;
}

// Raw tf32 mma: D(16x8) += A(16x8) * B(8x8)
__device__ __forceinline__ void mma_tf32(float* c, const uint4& a, const uint2& b) {
    asm volatile(
        "mma.sync.aligned.m16n8k8.row.col.f32.tf32.tf32.f32 "
        "{%0,%1,%2,%3},{%4,%5,%6,%7},{%8,%9},{%0,%1,%2,%3};"
        : "+f"(c[0]), "+f"(c[1]), "+f"(c[2]), "+f"(c[3])
        : "r"(a.x), "r"(a.y), "r"(a.z), "r"(a.w), "r"(b.x), "r"(b.y));
}

// ---------------------------------------------------------------------------
// Kernel -1: elementwise tf32 truncation (rna), float4-vectorized.
// ---------------------------------------------------------------------------
__global__ void convert_kernel(const float* __restrict__ in, float* __restrict__ outp, int n4)
{
    int i = blockIdx.x * blockDim.x + threadIdx.x;
    if (i < n4) *(float4*)&outp[i * 4] = tf32x4(*(const float4*)&in[i * 4]);
}

// ---------------------------------------------------------------------------
// Kernel 0: per-batch compaction of unmasked key indices (mask <= 0).
// ---------------------------------------------------------------------------
__global__ void compact_kernel(const int* __restrict__ mask)
{
    __shared__ int cnts[256];
    const int b = blockIdx.x;
    const int t = threadIdx.x;
    const int PER = SEQ / 256; // 8

    int m[PER];
    int local = 0;
#pragma unroll
    for (int i = 0; i < PER; i++) {
        m[i] = mask[b * SEQ + t * PER + i];
        local += (m[i] <= 0);
    }
    cnts[t] = local;
    __syncthreads();
    for (int off = 1; off < 256; off <<= 1) {
        int v = (t >= off) ? cnts[t - off] : 0;
        __syncthreads();
        cnts[t] += v;
        __syncthreads();
    }
    int w = cnts[t] - local;
#pragma unroll
    for (int i = 0; i < PER; i++)
        if (m[i] <= 0) g_idx[b * SEQ + (w++)] = t * PER + i;
    if (t == 255) g_cnt[b] = cnts[255];
}

// ---------------------------------------------------------------------------
// GEMM via raw mma + fragment-permuted smem.
// C[m,d] = sum_c A[m,c] * W[d,c]. Block 128(M) x 64(N), 4 warps (2x2),
// warp tile 64x32. BK=16 (2 k-steps of 8). Inputs pre-truncated to tf32.
//
// Permuted A layout: Asm[(s*8 + mt)*32 + lane][0..3] = thread 'lane' fragment
//   {A[g][c], A[g+8][c], A[g][c+4], A[g+8][c+4]} (g=lane>>2, c=lane&3) for
//   m-tile mt, k-step s  -> fragment load = 1 LDS.128.
// Permuted B layout: Bsm[(s*8 + nt)*32 + lane][0..1] = {B[c][n], B[c+4][n]}
//   (n=lane>>2, c=lane&3) -> fragment load = 1 LDS.64.
// ---------------------------------------------------------------------------
#define BKF 16
#define NCHUNK (DIM / BKF)   // 48
#define A_PERM_F (2 * 8 * 32 * 4)  // 2048 floats
#define B_PERM_F (2 * 8 * 32 * 2)  // 1024 floats

template <bool IS_QKV>
__global__ __launch_bounds__(128, 3) void tc_gemm_kernel(
    const float* __restrict__ bias, float* __restrict__ out)
{
    __shared__ float Asm[A_PERM_F];
    __shared__ float Bsm[B_PERM_F];

    const float* Ap = IS_QKV ? g_a : g_x;
    const float* Wp = IS_QKV ? g_wq : g_wf;

    const int tid = threadIdx.x;
    const int warp = tid >> 5;
    const int lane = tid & 31;
    const int wy = warp >> 1;   // 0..1 (m half)
    const int wx = warp & 1;    // 0..1 (n half)
    const int m0 = blockIdx.y << 7;
    const int d0 = blockIdx.x << 6;

    float acc[4][4][4];
#pragma unroll
    for (int i = 0; i < 4; i++)
#pragma unroll
        for (int j = 0; j < 4; j++)
#pragma unroll
            for (int e = 0; e < 4; e++) acc[i][j][e] = 0.f;

    // Staging geometry
    const int arow = tid >> 2;          // 0..31
    const int acol4 = (tid & 3) << 2;   // 0,4,8,12
    const int s_st = acol4 >> 3;        // k-step of this thread's 4 cols
    const int chi = (acol4 >> 2) & 1;   // col-high selector

    // A-permuted store bases for rows arow+32i (i=0..3)
    int abase[4];
#pragma unroll
    for (int i = 0; i < 4; i++) {
        int row = arow + 32 * i;
        int rr = row & 15, mt = row >> 4;
        int slot = (rr >> 3) + 2 * chi;
        abase[i] = ((s_st * 8 + mt) * 32 + ((rr & 7) << 2)) * 4 + slot;
    }
    // B-permuted store bases for rows arow+32i (i=0..1)
    int bbase[2];
#pragma unroll
    for (int i = 0; i < 2; i++) {
        int n = arow + 32 * i;
        bbase[i] = ((s_st * 8 + (n >> 3)) * 32 + ((n & 7) << 2)) * 2 + chi;
    }

    float4 pa[4], pw[2];
#pragma unroll
    for (int i = 0; i < 4; i++)
        pa[i] = *(const float4*)&Ap[(size_t)(m0 + arow + 32 * i) * DIM + acol4];
#pragma unroll
    for (int i = 0; i < 2; i++)
        pw[i] = *(const float4*)&Wp[(size_t)(d0 + arow + 32 * i) * DIM + acol4];

    for (int c = 0; c < NCHUNK; c++) {
        // Commit prefetched chunk into permuted smem
#pragma unroll
        for (int i = 0; i < 4; i++) {
            Asm[abase[i] + 0] = pa[i].x;
            Asm[abase[i] + 4] = pa[i].y;
            Asm[abase[i] + 8] = pa[i].z;
            Asm[abase[i] + 12] = pa[i].w;
        }
#pragma unroll
        for (int i = 0; i < 2; i++) {
            Bsm[bbase[i] + 0] = pw[i].x;
            Bsm[bbase[i] + 2] = pw[i].y;
            Bsm[bbase[i] + 4] = pw[i].z;
            Bsm[bbase[i] + 6] = pw[i].w;
        }
        __syncthreads();

        if (c + 1 < NCHUNK) {
            const int kc = (c + 1) * BKF;
#pragma unroll
            for (int i = 0; i < 4; i++)
                pa[i] = *(const float4*)&Ap[(size_t)(m0 + arow + 32 * i) * DIM + kc + acol4];
#pragma unroll
            for (int i = 0; i < 2; i++)
                pw[i] = *(const float4*)&Wp[(size_t)(d0 + arow + 32 * i) * DIM + kc + acol4];
        }

#pragma unroll
        for (int s = 0; s < 2; s++) {
            uint4 af[4];
            uint2 bf[4];
#pragma unroll
            for (int mt = 0; mt < 4; mt++)
                af[mt] = *(const uint4*)&Asm[((s * 8 + wy * 4 + mt) * 32 + lane) * 4];
#pragma unroll
            for (int nt = 0; nt < 4; nt++)
                bf[nt] = *(const uint2*)&Bsm[((s * 8 + wx * 4 + nt) * 32 + lane) * 2];
#pragma unroll
            for (int mt = 0; mt < 4; mt++)
#pragma unroll
                for (int nt = 0; nt < 4; nt++)
                    mma_tf32(acc[mt][nt], af[mt], bf[nt]);
        }
        __syncthreads();
    }

    // Epilogue. C fragment: c0=(g, q*2), c1=(g, q*2+1), c2=(g+8, q*2), c3=(g+8, q*2+1)
    const int g = lane >> 2;
    const int q2 = (lane & 3) << 1;

    if (IS_QKV) {
        const int bIdx = m0 >> 11;
        const int n0 = m0 & 2047;
        const int which = d0 / DIM;
        const int hbase = (d0 % DIM) >> 6;   // block N=64 lies in one head
        float* dstb = (which == 0) ? g_q : (which == 1) ? g_k : g_v;
        const size_t headbase = ((size_t)bIdx * NHEAD + hbase) * SEQ;
#pragma unroll
        for (int mt = 0; mt < 4; mt++)
#pragma unroll
            for (int nt = 0; nt < 4; nt++) {
                int n = n0 + wy * 64 + mt * 16 + g;
                int hd = wx * 32 + nt * 8 + q2;
                float2 lo = make_float2(wmma::__float_to_tf32(acc[mt][nt][0]),
                                        wmma::__float_to_tf32(acc[mt][nt][1]));
                float2 hi = make_float2(wmma::__float_to_tf32(acc[mt][nt][2]),
                                        wmma::__float_to_tf32(acc[mt][nt][3]));
                *(float2*)&dstb[(headbase + n) * HDIM + hd] = lo;
                *(float2*)&dstb[(headbase + n + 8) * HDIM + hd] = hi;
            }
    } else {
#pragma unroll
        for (int mt = 0; mt < 4; mt++)
#pragma unroll
            for (int nt = 0; nt < 4; nt++) {
                int m = m0 + wy * 64 + mt * 16 + g;
                int d = d0 + wx * 32 + nt * 8 + q2;
                float2 bv = *(const float2*)&bias[d];
                float2 lo = make_float2(acc[mt][nt][0] + bv.x, acc[mt][nt][1] + bv.y);
                float2 hi = make_float2(acc[mt][nt][2] + bv.x, acc[mt][nt][3] + bv.y);
                *(float2*)&out[(size_t)m * DIM + d] = lo;
                *(float2*)&out[(size_t)(m + 8) * DIM + d] = hi;
            }
    }
}

// ---------------------------------------------------------------------------
// Kernel 2: flash attention (tf32 wmma) over compacted keys. (R8, unchanged)
// ---------------------------------------------------------------------------
__global__ __launch_bounds__(256) void attn_kernel()
{
    __shared__ float buf1[128 * 68];
    __shared__ float KVs[32 * 68];
    __shared__ float lsum[128];
    __shared__ float meanv[64];

    const int tid = threadIdx.x;
    const int warp = tid >> 5;
    const int bh = blockIdx.y;
    const int b = bh / NHEAD, h = bh % NHEAD;
    const int q0 = blockIdx.x * 128;
    const float* qb = g_q + (size_t)bh * SEQ * HDIM;
    const float* kb = g_k + (size_t)bh * SEQ * HDIM;
    const float* vb = g_v + (size_t)bh * SEQ * HDIM;
    const int cnt = g_cnt[b];
    const int* idxb = g_idx + b * SEQ;

    if (cnt == 0) {
        if (tid < 64) {
            float acc = 0.f;
            for (int k = 0; k < SEQ; k++) acc += vb[(size_t)k * HDIM + tid];
            meanv[tid] = wmma::__float_to_tf32(acc / (float)SEQ);
        }
        __syncthreads();
        int row = tid >> 1, half = tid & 1;
        float* dst = g_x + (size_t)(b * SEQ + q0 + row) * DIM + h * HDIM + half * 32;
#pragma unroll
        for (int c = 0; c < 32; c++) dst[c] = meanv[half * 32 + c];
        return;
    }

    const int lr = tid >> 4;
    const int gc4 = (tid & 15) << 2;

#pragma unroll
    for (int i = 0; i < 8; i++) {
        int r = lr + 16 * i;
        *(float4*)&buf1[r * 68 + gc4] = *(const float4*)&qb[(size_t)(q0 + r) * HDIM + gc4];
    }
    if (tid < 128) lsum[tid] = 0.f;
    __syncthreads();

    AFrag aq[8];
#pragma unroll
    for (int ks = 0; ks < 8; ks++)
        wmma::load_matrix_sync(aq[ks], &buf1[(warp * 16) * 68 + ks * 8], 68);

    CFrag ofrag[4];
#pragma unroll
    for (int dn = 0; dn < 4; dn++) wmma::fill_fragment(ofrag[dn], 0.f);

    const int ntiles = (cnt + 31) >> 5;

    int src[2];
    float4 kreg[2];
#pragma unroll
    for (int i = 0; i < 2; i++) {
        int r = lr + 16 * i;
        src[i] = (r < cnt) ? __ldg(&idxb[r]) : 0;
        kreg[i] = *(const float4*)&kb[(size_t)src[i] * HDIM + gc4];
    }

    for (int tile = 0; tile < ntiles; tile++) {
        const int k0 = tile << 5;
        __syncthreads();

#pragma unroll
        for (int i = 0; i < 2; i++)
            *(float4*)&KVs[(lr + 16 * i) * 68 + gc4] = kreg[i];
        __syncthreads();

        float4 vreg[2];
#pragma unroll
        for (int i = 0; i < 2; i++)
            vreg[i] = *(const float4*)&vb[(size_t)src[i] * HDIM + gc4];

        CFrag sfrag[2];
#pragma unroll
        for (int jn = 0; jn < 2; jn++) wmma::fill_fragment(sfrag[jn], 0.f);
#pragma unroll
        for (int ks = 0; ks < 8; ks++) {
#pragma unroll
            for (int jn = 0; jn < 2; jn++) {
                BFragCol bk;
                wmma::load_matrix_sync(bk, &KVs[(jn * 16) * 68 + ks * 8], 68);
                wmma::mma_sync(sfrag[jn], aq[ks], bk, sfrag[jn]);
            }
        }
#pragma unroll
        for (int jn = 0; jn < 2; jn++)
            wmma::store_matrix_sync(&buf1[(warp * 16) * 68 + jn * 16], sfrag[jn], 68,
                                    wmma::mem_row_major);
        __syncthreads();

        {
            const int row = tid >> 1, half = tid & 1;
            const int valid = cnt - k0;
            float* er = &buf1[row * 68 + half * 16];
            float ps = 0.f;
#pragma unroll
            for (int c4 = 0; c4 < 16; c4 += 4) {
                float4 v = *(float4*)&er[c4];
                int jb = half * 16 + c4;
                v.x = (jb + 0 < valid) ? __expf(v.x * SCALE) : 0.f;
                v.y = (jb + 1 < valid) ? __expf(v.y * SCALE) : 0.f;
                v.z = (jb + 2 < valid) ? __expf(v.z * SCALE) : 0.f;
                v.w = (jb + 3 < valid) ? __expf(v.w * SCALE) : 0.f;
                ps += v.x + v.y + v.z + v.w;
                *(float4*)&er[c4] = tf32x4(v);
            }
            ps += __shfl_xor_sync(0xffffffffu, ps, 1);
            if (half == 0) lsum[row] += ps;
        }

#pragma unroll
        for (int i = 0; i < 2; i++)
            *(float4*)&KVs[(lr + 16 * i) * 68 + gc4] = vreg[i];

        if (tile + 1 < ntiles) {
            const int kn = k0 + 32;
#pragma unroll
            for (int i = 0; i < 2; i++) {
                int g = kn + lr + 16 * i;
                src[i] = (g < cnt) ? __ldg(&idxb[g]) : 0;
                kreg[i] = *(const float4*)&kb[(size_t)src[i] * HDIM + gc4];
            }
        }
        __syncthreads();

#pragma unroll
        for (int js = 0; js < 4; js++) {
            AFrag ap;
            wmma::load_matrix_sync(ap, &buf1[(warp * 16) * 68 + js * 8], 68);
#pragma unroll
            for (int dn = 0; dn < 4; dn++) {
                BFragRow bv;
                wmma::load_matrix_sync(bv, &KVs[(js * 8) * 68 + dn * 16], 68);
                wmma::mma_sync(ofrag[dn], ap, bv, ofrag[dn]);
            }
        }
    }

    __syncthreads();
#pragma unroll
    for (int dn = 0; dn < 4; dn++)
        wmma::store_matrix_sync(&buf1[(warp * 16) * 68 + dn * 16], ofrag[dn], 68,
                                wmma::mem_row_major);
    __syncthreads();

    {
        const int row = tid >> 1, half = tid & 1;
        const float inv = 1.f / lsum[row];
        const float* srcp = &buf1[row * 68 + half * 32];
        float* dst = g_x + (size_t)(b * SEQ + q0 + row) * DIM + h * HDIM + half * 32;
#pragma unroll
        for (int c4 = 0; c4 < 32; c4 += 4) {
            float4 v = *(const float4*)&srcp[c4];
            v = make_float4(v.x * inv, v.y * inv, v.z * inv, v.w * inv);
            *(float4*)&dst[c4] = tf32x4(v);
        }
    }
}

// ---------------------------------------------------------------------------
// Launch
// ---------------------------------------------------------------------------
extern "C" void kernel_launch(void* const* d_in, const int* in_sizes, int n_in,
                              void* d_out, int out_size)
{
    const float* inputs = (const float*)d_in[0];
    const int*   pmask  = (const int*)d_in[1];
    const float* w_qkv  = (const float*)d_in[2];
    const float* w_fc   = (const float*)d_in[3];
    const float* b_fc   = (const float*)d_in[4];
    float* out = (float*)d_out;

    float* da;  cudaGetSymbolAddress((void**)&da, g_a);
    float* dwq; cudaGetSymbolAddress((void**)&dwq, g_wq);
    float* dwf; cudaGetSymbolAddress((void**)&dwf, g_wf);

    compact_kernel<<<BATCH, 256>>>(pmask);
    {
        int n4 = M_TOTAL * DIM / 4;
        convert_kernel<<<(n4 + 255) / 256, 256>>>(inputs, da, n4);
        n4 = QKV_DIM * DIM / 4;
        convert_kernel<<<(n4 + 255) / 256, 256>>>(w_qkv, dwq, n4);
        n4 = DIM * DIM / 4;
        convert_kernel<<<(n4 + 255) / 256, 256>>>(w_fc, dwf, n4);
    }
    {
        dim3 grid(QKV_DIM / 64, M_TOTAL / 128); // (36, 32) = 1152 CTAs
        tc_gemm_kernel<true><<<grid, 128>>>(nullptr, nullptr);
    }
    {
        dim3 grid(SEQ / 128, BATCH * NHEAD);    // (16, 24)
        attn_kernel<<<grid, 256>>>();
    }
    {
        dim3 grid(DIM / 64, M_TOTAL / 128);     // (12, 32) = 384 CTAs
        tc_gemm_kernel<false><<<grid, 128>>>(b_fc, out);
    }
}

// round 10
// speedup vs baseline: 1.1278x; 1.1278x over previous
#include <cuda_runtime.h>
#include <mma.h>
#include <math.h>
#include <stdint.h>

using namespace nvcuda;

// Problem constants
#define BATCH 2
#define SEQ 2048
#define DIM 768
#define NHEAD 12
#define HDIM 64
#define QKV_DIM (3 * DIM)     // 2304
#define M_TOTAL (BATCH * SEQ) // 4096
#define SCALE 0.125f          // 64^-0.5

// Scratch (device globals; no allocations allowed)
__device__ float g_q[BATCH * NHEAD * SEQ * HDIM];
__device__ float g_k[BATCH * NHEAD * SEQ * HDIM];
__device__ float g_v[BATCH * NHEAD * SEQ * HDIM];
__device__ float g_x[M_TOTAL * DIM];
__device__ int   g_idx[BATCH * SEQ];
__device__ int   g_cnt[BATCH];

typedef wmma::fragment<wmma::matrix_a, 16, 16, 8, wmma::precision::tf32, wmma::row_major> AFrag;
typedef wmma::fragment<wmma::matrix_b, 16, 16, 8, wmma::precision::tf32, wmma::col_major> BFragCol;
typedef wmma::fragment<wmma::matrix_b, 16, 16, 8, wmma::precision::tf32, wmma::row_major> BFragRow;
typedef wmma::fragment<wmma::accumulator, 16, 16, 8, float> CFrag;

__device__ __forceinline__ float4 tf32x4(float4 v) {
    v.x = wmma::__float_to_tf32(v.x);
    v.y = wmma::__float_to_tf32(v.y);
    v.z = wmma::__float_to_tf32(v.z);
    v.w = wmma::__float_to_tf32(v.w);
    return v;
}

// ---------------------------------------------------------------------------
// Kernel 0: per-batch compaction of unmasked key indices (mask <= 0).
// Masked keys get score -1e7; exp underflows to exactly 0 in fp32, so
// dropping them is numerically identical to the reference.
// ---------------------------------------------------------------------------
__global__ void compact_kernel(const int* __restrict__ mask)
{
    __shared__ int cnts[256];
    const int b = blockIdx.x;
    const int t = threadIdx.x;
    const int PER = SEQ / 256; // 8

    int m[PER];
    int local = 0;
#pragma unroll
    for (int i = 0; i < PER; i++) {
        m[i] = mask[b * SEQ + t * PER + i];
        local += (m[i] <= 0);
    }
    cnts[t] = local;
    __syncthreads();
    for (int off = 1; off < 256; off <<= 1) {
        int v = (t >= off) ? cnts[t - off] : 0;
        __syncthreads();
        cnts[t] += v;
        __syncthreads();
    }
    int w = cnts[t] - local;
#pragma unroll
    for (int i = 0; i < PER; i++)
        if (m[i] <= 0) g_idx[b * SEQ + (w++)] = t * PER + i;
    if (t == 255) g_cnt[b] = cnts[255];
}

#define BK 16
#define LDA 20  // 16 + 4 pad

// ---------------------------------------------------------------------------
// Kernel 1: QKV projection (exact R6 best-measured version).
// 128x128 block tile, 4 warps (2x2), warp tile 64x64, register prefetch.
// ---------------------------------------------------------------------------
__global__ __launch_bounds__(128) void qkv_kernel(
    const float* __restrict__ A, const float* __restrict__ W)
{
    __shared__ float As[128 * LDA];
    __shared__ float Ws[128 * LDA];

    const int tid = threadIdx.x;
    const int w = tid >> 5;
    const int wy = w >> 1;
    const int wx = w & 1;
    const int m0 = blockIdx.y << 7;
    const int d0 = blockIdx.x << 7;

    CFrag acc[4][4];
#pragma unroll
    for (int i = 0; i < 4; i++)
#pragma unroll
        for (int j = 0; j < 4; j++) wmma::fill_fragment(acc[i][j], 0.f);

    const int ar = tid >> 2;
    const int ac4 = (tid & 3) << 2;

    float4 pa[4], pw[4];
#pragma unroll
    for (int i = 0; i < 4; i++) {
        pa[i] = *(const float4*)&A[(size_t)(m0 + ar + 32 * i) * DIM + ac4];
        pw[i] = *(const float4*)&W[(size_t)(d0 + ar + 32 * i) * DIM + ac4];
    }

    for (int kc = 0; kc < DIM; kc += BK) {
#pragma unroll
        for (int i = 0; i < 4; i++) {
            *(float4*)&As[(ar + 32 * i) * LDA + ac4] = tf32x4(pa[i]);
            *(float4*)&Ws[(ar + 32 * i) * LDA + ac4] = tf32x4(pw[i]);
        }
        __syncthreads();
        if (kc + BK < DIM) {
#pragma unroll
            for (int i = 0; i < 4; i++) {
                pa[i] = *(const float4*)&A[(size_t)(m0 + ar + 32 * i) * DIM + kc + BK + ac4];
                pw[i] = *(const float4*)&W[(size_t)(d0 + ar + 32 * i) * DIM + kc + BK + ac4];
            }
        }
#pragma unroll
        for (int ks = 0; ks < 2; ks++) {
            AFrag am[4];
            BFragCol bn[4];
#pragma unroll
            for (int ms = 0; ms < 4; ms++)
                wmma::load_matrix_sync(am[ms], &As[(wy * 64 + ms * 16) * LDA + ks * 8], LDA);
#pragma unroll
            for (int ns = 0; ns < 4; ns++)
                wmma::load_matrix_sync(bn[ns], &Ws[(wx * 64 + ns * 16) * LDA + ks * 8], LDA);
#pragma unroll
            for (int ms = 0; ms < 4; ms++)
#pragma unroll
                for (int ns = 0; ns < 4; ns++)
                    wmma::mma_sync(acc[ms][ns], am[ms], bn[ns], acc[ms][ns]);
        }
        __syncthreads();
    }

    const int bIdx = m0 >> 11;
    const int n0 = (m0 & 2047) + wy * 64;
    const int dg = d0 + wx * 64;
    const int which = dg / DIM;
    float* dstb = (which == 0) ? g_q : (which == 1) ? g_k : g_v;

#pragma unroll
    for (int ms = 0; ms < 4; ms++)
#pragma unroll
        for (int ns = 0; ns < 4; ns++) {
#pragma unroll
            for (int e = 0; e < acc[ms][ns].num_elements; e++)
                acc[ms][ns].x[e] = wmma::__float_to_tf32(acc[ms][ns].x[e]);
            int dl = (dg % DIM) + ns * 16;
            int h = dl >> 6, hd = dl & 63;
            float* p = dstb + (((size_t)bIdx * NHEAD + h) * SEQ + n0 + ms * 16) * HDIM + hd;
            wmma::store_matrix_sync(p, acc[ms][ns], HDIM, wmma::mem_row_major);
        }
}

// ---------------------------------------------------------------------------
// Kernel 2: flash attention (tf32 wmma) over compacted keys.
// 128 query rows/block (256 thr, 8 warps), 64-row KV tiles.
// Dynamic smem: Qs (persistent), Eb (S/E/O), Ks, Vs separate buffers.
// ONLY 2 block barriers per tile; exp and PV chains are warp-local
// (warp w touches E rows 16w..16w+15 only) -> __syncwarp suffices.
// ---------------------------------------------------------------------------
#define QS_OFF 0
#define EB_OFF (128 * 68)                 // 8704
#define KS_OFF (EB_OFF + 128 * 68)        // 17408
#define VS_OFF (KS_OFF + 64 * 68)         // 21760
#define LS_OFF (VS_OFF + 64 * 68)         // 26112
#define MV_OFF (LS_OFF + 128)             // 26240
#define ATTN_SMEM_F (MV_OFF + 64)         // 26304 floats
#define ATTN_SMEM_B (ATTN_SMEM_F * 4)     // 105216 bytes

__global__ __launch_bounds__(256, 2) void attn_kernel()
{
    extern __shared__ float dyn[];
    float* Qs = dyn + QS_OFF;
    float* Eb = dyn + EB_OFF;
    float* Ks = dyn + KS_OFF;
    float* Vs = dyn + VS_OFF;
    float* lsum = dyn + LS_OFF;
    float* meanv = dyn + MV_OFF;

    const int tid = threadIdx.x;
    const int warp = tid >> 5;
    const int bh = blockIdx.y;
    const int b = bh / NHEAD, h = bh % NHEAD;
    const int q0 = blockIdx.x * 128;
    const float* qb = g_q + (size_t)bh * SEQ * HDIM;
    const float* kb = g_k + (size_t)bh * SEQ * HDIM;
    const float* vb = g_v + (size_t)bh * SEQ * HDIM;
    const int cnt = g_cnt[b];
    const int* idxb = g_idx + b * SEQ;

    if (cnt == 0) {
        // All keys masked: softmax uniform -> output = mean of V rows.
        if (tid < 64) {
            float acc = 0.f;
            for (int k = 0; k < SEQ; k++) acc += vb[(size_t)k * HDIM + tid];
            meanv[tid] = acc / (float)SEQ;
        }
        __syncthreads();
        int row = tid >> 1, half = tid & 1;
        float* dst = g_x + (size_t)(b * SEQ + q0 + row) * DIM + h * HDIM + half * 32;
#pragma unroll
        for (int c = 0; c < 32; c++) dst[c] = meanv[half * 32 + c];
        return;
    }

    const int lr = tid >> 4;            // 0..15
    const int gc4 = (tid & 15) << 2;    // 0..60

    // Load Q tile (128 x 64) into persistent Qs
#pragma unroll
    for (int i = 0; i < 8; i++) {
        int r = lr + 16 * i;
        *(float4*)&Qs[r * 68 + gc4] = *(const float4*)&qb[(size_t)(q0 + r) * HDIM + gc4];
    }
    if (tid < 128) lsum[tid] = 0.f;

    CFrag ofrag[4];
#pragma unroll
    for (int dn = 0; dn < 4; dn++) wmma::fill_fragment(ofrag[dn], 0.f);

    const int ntiles = (cnt + 63) >> 6;

    // Prologue: gather indices + K/V tile 0 (64 rows x 64 cols)
    int src[4];
    float4 kreg[4], vreg[4];
#pragma unroll
    for (int i = 0; i < 4; i++) {
        int r = lr + 16 * i;
        src[i] = (r < cnt) ? __ldg(&idxb[r]) : 0;
        kreg[i] = *(const float4*)&kb[(size_t)src[i] * HDIM + gc4];
        vreg[i] = *(const float4*)&vb[(size_t)src[i] * HDIM + gc4];
    }

    for (int tile = 0; tile < ntiles; tile++) {
        const int k0 = tile << 6;
        __syncthreads(); // prev-tile PV reads of Vs/Eb done (1st iter: trivial)

#pragma unroll
        for (int i = 0; i < 4; i++) {
            *(float4*)&Ks[(lr + 16 * i) * 68 + gc4] = kreg[i];
            *(float4*)&Vs[(lr + 16 * i) * 68 + gc4] = vreg[i];
        }
        __syncthreads(); // K/V (and first-iter Q) visible

        // Prefetch next tile gathers — overlap with S + exp + PV
        if (tile + 1 < ntiles) {
            const int kn = k0 + 64;
#pragma unroll
            for (int i = 0; i < 4; i++) {
                int g = kn + lr + 16 * i;
                src[i] = (g < cnt) ? __ldg(&idxb[g]) : 0;
                kreg[i] = *(const float4*)&kb[(size_t)src[i] * HDIM + gc4];
                vreg[i] = *(const float4*)&vb[(size_t)src[i] * HDIM + gc4];
            }
        }

        // S = Q K^T for this warp's 16-row strip (16 x 64)
        CFrag sfrag[4];
#pragma unroll
        for (int jn = 0; jn < 4; jn++) wmma::fill_fragment(sfrag[jn], 0.f);
#pragma unroll
        for (int ks = 0; ks < 8; ks++) {
            AFrag aq;
            wmma::load_matrix_sync(aq, &Qs[(warp * 16) * 68 + ks * 8], 68);
#pragma unroll
            for (int jn = 0; jn < 4; jn++) {
                BFragCol bk;
                wmma::load_matrix_sync(bk, &Ks[(jn * 16) * 68 + ks * 8], 68);
                wmma::mma_sync(sfrag[jn], aq, bk, sfrag[jn]);
            }
        }
#pragma unroll
        for (int jn = 0; jn < 4; jn++)
            wmma::store_matrix_sync(&Eb[(warp * 16) * 68 + jn * 16], sfrag[jn], 68,
                                    wmma::mem_row_major);
        __syncwarp(); // E strip is warp-local

        // Elementwise exp (+ mask tail), tf32-truncate, row-sum accumulate.
        // Thread handles row tid>>1 (within own warp's strip), 32 cols.
        {
            const int row = tid >> 1, half = tid & 1;
            const int valid = cnt - k0;
            float* er = &Eb[row * 68 + half * 32];
            float ps = 0.f;
#pragma unroll
            for (int c4 = 0; c4 < 32; c4 += 4) {
                float4 v = *(float4*)&er[c4];
                int jb = half * 32 + c4;
                v.x = (jb + 0 < valid) ? __expf(v.x * SCALE) : 0.f;
                v.y = (jb + 1 < valid) ? __expf(v.y * SCALE) : 0.f;
                v.z = (jb + 2 < valid) ? __expf(v.z * SCALE) : 0.f;
                v.w = (jb + 3 < valid) ? __expf(v.w * SCALE) : 0.f;
                ps += v.x + v.y + v.z + v.w;
                *(float4*)&er[c4] = tf32x4(v);
            }
            ps += __shfl_xor_sync(0xffffffffu, ps, 1);
            if (half == 0) lsum[row] += ps;
        }
        __syncwarp(); // E updates warp-local

        // O += E V  (E 16x64 per warp, V 64x64)
#pragma unroll
        for (int js = 0; js < 8; js++) {
            AFrag ap;
            wmma::load_matrix_sync(ap, &Eb[(warp * 16) * 68 + js * 8], 68);
#pragma unroll
            for (int dn = 0; dn < 4; dn++) {
                BFragRow bv;
                wmma::load_matrix_sync(bv, &Vs[(js * 8) * 68 + dn * 16], 68);
                wmma::mma_sync(ofrag[dn], ap, bv, ofrag[dn]);
            }
        }
    }

    __syncthreads();
#pragma unroll
    for (int dn = 0; dn < 4; dn++)
        wmma::store_matrix_sync(&Eb[(warp * 16) * 68 + dn * 16], ofrag[dn], 68,
                                wmma::mem_row_major);
    __syncwarp();

    {
        const int row = tid >> 1, half = tid & 1;
        const float inv = 1.f / lsum[row];
        const float* srcp = &Eb[row * 68 + half * 32];
        float* dst = g_x + (size_t)(b * SEQ + q0 + row) * DIM + h * HDIM + half * 32;
#pragma unroll
        for (int c4 = 0; c4 < 32; c4 += 4) {
            float4 v = *(const float4*)&srcp[c4];
            *(float4*)&dst[c4] = make_float4(v.x * inv, v.y * inv, v.z * inv, v.w * inv);
        }
    }
}

// ---------------------------------------------------------------------------
// Kernel 3: FC projection (exact R6 best-measured version).
// ---------------------------------------------------------------------------
__global__ __launch_bounds__(128, 3) void fc_kernel(
    const float* __restrict__ W, float* __restrict__ out)
{
    __shared__ float As[2][128 * LDA];
    __shared__ float Ws[2][64 * LDA];

    const int tid = threadIdx.x;
    const int w = tid >> 5;
    const int wy = w >> 1;
    const int wx = w & 1;
    const int m0 = blockIdx.y << 7;
    const int d0 = blockIdx.x << 6;

    CFrag acc[4][2];
#pragma unroll
    for (int i = 0; i < 4; i++)
#pragma unroll
        for (int j = 0; j < 2; j++) wmma::fill_fragment(acc[i][j], 0.f);

    const int ar = tid >> 2;
    const int ac4 = (tid & 3) << 2;

    float4 pa[4], pw[2];
#pragma unroll
    for (int i = 0; i < 4; i++)
        pa[i] = *(const float4*)&g_x[(size_t)(m0 + ar + 32 * i) * DIM + ac4];
#pragma unroll
    for (int i = 0; i < 2; i++)
        pw[i] = *(const float4*)&W[(size_t)(d0 + ar + 32 * i) * DIM + ac4];
#pragma unroll
    for (int i = 0; i < 4; i++)
        *(float4*)&As[0][(ar + 32 * i) * LDA + ac4] = tf32x4(pa[i]);
#pragma unroll
    for (int i = 0; i < 2; i++)
        *(float4*)&Ws[0][(ar + 32 * i) * LDA + ac4] = tf32x4(pw[i]);
    __syncthreads();

    int buf = 0;
    for (int kc = 0; kc < DIM; kc += BK) {
        const bool more = (kc + BK < DIM);
        if (more) {
#pragma unroll
            for (int i = 0; i < 4; i++)
                pa[i] = *(const float4*)&g_x[(size_t)(m0 + ar + 32 * i) * DIM + kc + BK + ac4];
#pragma unroll
            for (int i = 0; i < 2; i++)
                pw[i] = *(const float4*)&W[(size_t)(d0 + ar + 32 * i) * DIM + kc + BK + ac4];
        }
#pragma unroll
        for (int ks = 0; ks < 2; ks++) {
            AFrag am[4];
            BFragCol bn[2];
#pragma unroll
            for (int ms = 0; ms < 4; ms++)
                wmma::load_matrix_sync(am[ms], &As[buf][(wy * 64 + ms * 16) * LDA + ks * 8], LDA);
#pragma unroll
            for (int ns = 0; ns < 2; ns++)
                wmma::load_matrix_sync(bn[ns], &Ws[buf][(wx * 32 + ns * 16) * LDA + ks * 8], LDA);
#pragma unroll
            for (int ms = 0; ms < 4; ms++)
#pragma unroll
                for (int ns = 0; ns < 2; ns++)
                    wmma::mma_sync(acc[ms][ns], am[ms], bn[ns], acc[ms][ns]);
        }
        if (more) {
#pragma unroll
            for (int i = 0; i < 4; i++)
                *(float4*)&As[buf ^ 1][(ar + 32 * i) * LDA + ac4] = tf32x4(pa[i]);
#pragma unroll
            for (int i = 0; i < 2; i++)
                *(float4*)&Ws[buf ^ 1][(ar + 32 * i) * LDA + ac4] = tf32x4(pw[i]);
            __syncthreads();
            buf ^= 1;
        }
    }

#pragma unroll
    for (int ms = 0; ms < 4; ms++)
#pragma unroll
        for (int ns = 0; ns < 2; ns++) {
            float* p = out + (size_t)(m0 + wy * 64 + ms * 16) * DIM + d0 + wx * 32 + ns * 16;
            wmma::store_matrix_sync(p, acc[ms][ns], DIM, wmma::mem_row_major);
        }
}

// Bias add
__global__ void bias_kernel(float* __restrict__ out, const float* __restrict__ bias)
{
    int i4 = blockIdx.x * blockDim.x + threadIdx.x;
    const int total4 = M_TOTAL * DIM / 4;
    if (i4 >= total4) return;
    int col4 = (i4 % (DIM / 4)) << 2;
    float4 v = *(float4*)&out[i4 * 4];
    float4 bv = *(const float4*)&bias[col4];
    v.x += bv.x; v.y += bv.y; v.z += bv.z; v.w += bv.w;
    *(float4*)&out[i4 * 4] = v;
}

// ---------------------------------------------------------------------------
// Launch
// ---------------------------------------------------------------------------
extern "C" void kernel_launch(void* const* d_in, const int* in_sizes, int n_in,
                              void* d_out, int out_size)
{
    const float* inputs = (const float*)d_in[0];
    const int*   pmask  = (const int*)d_in[1];
    const float* w_qkv  = (const float*)d_in[2];
    const float* w_fc   = (const float*)d_in[3];
    const float* b_fc   = (const float*)d_in[4];
    float* out = (float*)d_out;

    cudaFuncSetAttribute(attn_kernel,
                         cudaFuncAttributeMaxDynamicSharedMemorySize, ATTN_SMEM_B);

    compact_kernel<<<BATCH, 256>>>(pmask);
    {
        dim3 grid(QKV_DIM / 128, M_TOTAL / 128); // (18, 32) = 576 CTAs
        qkv_kernel<<<grid, 128>>>(inputs, w_qkv);
    }
    {
        dim3 grid(SEQ / 128, BATCH * NHEAD);     // (16, 24) = 384 CTAs
        attn_kernel<<<grid, 256, ATTN_SMEM_B>>>();
    }
    {
        dim3 grid(DIM / 64, M_TOTAL / 128);      // (12, 32) = 384 CTAs
        fc_kernel<<<grid, 128>>>(w_fc, out);
    }
    {
        int total4 = M_TOTAL * DIM / 4;
        bias_kernel<<<(total4 + 255) / 256, 256>>>(out, b_fc);
    }
}

// round 11
// speedup vs baseline: 3.3619x; 2.9809x over previous
#include <cuda_runtime.h>
#include <cuda_fp16.h>
#include <mma.h>
#include <math.h>
#include <stdint.h>

using namespace nvcuda;

// Problem constants
#define BATCH 2
#define SEQ 2048
#define DIM 768
#define NHEAD 12
#define HDIM 64
#define QKV_DIM (3 * DIM)     // 2304
#define M_TOTAL (BATCH * SEQ) // 4096
#define SCALE 0.125f          // 64^-0.5

// Scratch (device globals; no allocations allowed)
__device__ __half g_q[BATCH * NHEAD * SEQ * HDIM];
__device__ __half g_k[BATCH * NHEAD * SEQ * HDIM];
__device__ __half g_v[BATCH * NHEAD * SEQ * HDIM];
__device__ __half g_x[M_TOTAL * DIM];
__device__ __half g_a[M_TOTAL * DIM];     // fp16-rounded inputs
__device__ __half g_wq[QKV_DIM * DIM];    // fp16-rounded w_qkv
__device__ __half g_wf[DIM * DIM];        // fp16-rounded w_fc
__device__ int    g_idx[BATCH * SEQ];
__device__ int    g_cnt[BATCH];

typedef wmma::fragment<wmma::matrix_a, 16, 16, 16, __half, wmma::row_major> HA;
typedef wmma::fragment<wmma::matrix_b, 16, 16, 16, __half, wmma::col_major> HBc;
typedef wmma::fragment<wmma::matrix_b, 16, 16, 16, __half, wmma::row_major> HBr;
typedef wmma::fragment<wmma::accumulator, 16, 16, 16, float> HC;

// ---------------------------------------------------------------------------
// Kernel -1: fp32 -> fp16 round-to-nearest, 8 elems/thread.
// ---------------------------------------------------------------------------
__global__ void convert_kernel(const float* __restrict__ in, __half* __restrict__ outp, int n8)
{
    int i = blockIdx.x * blockDim.x + threadIdx.x;
    if (i >= n8) return;
    float4 a = *(const float4*)&in[i * 8];
    float4 b = *(const float4*)&in[i * 8 + 4];
    __half2 h0 = __floats2half2_rn(a.x, a.y);
    __half2 h1 = __floats2half2_rn(a.z, a.w);
    __half2 h2 = __floats2half2_rn(b.x, b.y);
    __half2 h3 = __floats2half2_rn(b.z, b.w);
    uint4 u;
    u.x = *(uint32_t*)&h0; u.y = *(uint32_t*)&h1;
    u.z = *(uint32_t*)&h2; u.w = *(uint32_t*)&h3;
    *(uint4*)&outp[i * 8] = u;
}

// ---------------------------------------------------------------------------
// Kernel 0: per-batch compaction of unmasked key indices (mask <= 0).
// Masked keys get score -1e7; exp underflows to exactly 0 in fp32, so
// dropping them is numerically identical to the reference.
// ---------------------------------------------------------------------------
__global__ void compact_kernel(const int* __restrict__ mask)
{
    __shared__ int cnts[256];
    const int b = blockIdx.x;
    const int t = threadIdx.x;
    const int PER = SEQ / 256; // 8

    int m[PER];
    int local = 0;
#pragma unroll
    for (int i = 0; i < PER; i++) {
        m[i] = mask[b * SEQ + t * PER + i];
        local += (m[i] <= 0);
    }
    cnts[t] = local;
    __syncthreads();
    for (int off = 1; off < 256; off <<= 1) {
        int v = (t >= off) ? cnts[t - off] : 0;
        __syncthreads();
        cnts[t] += v;
        __syncthreads();
    }
    int w = cnts[t] - local;
#pragma unroll
    for (int i = 0; i < PER; i++)
        if (m[i] <= 0) g_idx[b * SEQ + (w++)] = t * PER + i;
    if (t == 255) g_cnt[b] = cnts[255];
}

// ---------------------------------------------------------------------------
// fp16 GEMM config: BK=32 halves per chunk, LDH=40 (80B rows, LDSM-friendly,
// conflict-free: 8 consecutive rows hit 8 distinct bank groups).
// ---------------------------------------------------------------------------
#define BK 32
#define LDH 40
#define NCHUNK (DIM / BK)  // 24

// ---------------------------------------------------------------------------
// Kernel 1: QKV projection (fp16 wmma). C[m,d] = sum_c A[m,c] * W[d,c].
// 128x128 block tile, 4 warps (2x2), warp tile 64x64, register prefetch.
// Epilogue stages each fragment through smem and scatters fp16 into
// [b,h,n,hd] layout.
// ---------------------------------------------------------------------------
__global__ __launch_bounds__(128) void qkv_kernel()
{
    __shared__ __half As[128 * LDH];
    __shared__ __half Ws[128 * LDH];

    const int tid = threadIdx.x;
    const int warp = tid >> 5;
    const int lane = tid & 31;
    const int wy = warp >> 1;
    const int wx = warp & 1;
    const int m0 = blockIdx.y << 7;
    const int d0 = blockIdx.x << 7;

    HC acc[4][4];
#pragma unroll
    for (int i = 0; i < 4; i++)
#pragma unroll
        for (int j = 0; j < 4; j++) wmma::fill_fragment(acc[i][j], 0.f);

    const int ar = tid >> 2;          // 0..31
    const int ac8 = (tid & 3) << 3;   // 0,8,16,24 (halves)

    uint4 pa[4], pw[4];
#pragma unroll
    for (int i = 0; i < 4; i++) {
        pa[i] = *(const uint4*)&g_a[(size_t)(m0 + ar + 32 * i) * DIM + ac8];
        pw[i] = *(const uint4*)&g_wq[(size_t)(d0 + ar + 32 * i) * DIM + ac8];
    }

    for (int c = 0; c < NCHUNK; c++) {
#pragma unroll
        for (int i = 0; i < 4; i++) {
            *(uint4*)&As[(ar + 32 * i) * LDH + ac8] = pa[i];
            *(uint4*)&Ws[(ar + 32 * i) * LDH + ac8] = pw[i];
        }
        __syncthreads();
        if (c + 1 < NCHUNK) {
            const int kc = (c + 1) * BK;
#pragma unroll
            for (int i = 0; i < 4; i++) {
                pa[i] = *(const uint4*)&g_a[(size_t)(m0 + ar + 32 * i) * DIM + kc + ac8];
                pw[i] = *(const uint4*)&g_wq[(size_t)(d0 + ar + 32 * i) * DIM + kc + ac8];
            }
        }
#pragma unroll
        for (int ks = 0; ks < 2; ks++) {
            HA am[4];
            HBc bn[4];
#pragma unroll
            for (int ms = 0; ms < 4; ms++)
                wmma::load_matrix_sync(am[ms], &As[(wy * 64 + ms * 16) * LDH + ks * 16], LDH);
#pragma unroll
            for (int ns = 0; ns < 4; ns++)
                wmma::load_matrix_sync(bn[ns], &Ws[(wx * 64 + ns * 16) * LDH + ks * 16], LDH);
#pragma unroll
            for (int ms = 0; ms < 4; ms++)
#pragma unroll
                for (int ns = 0; ns < 4; ns++)
                    wmma::mma_sync(acc[ms][ns], am[ms], bn[ns], acc[ms][ns]);
        }
        __syncthreads();
    }

    // Epilogue: per-warp smem staging (reuse As), convert to fp16, scatter.
    float* Ep = (float*)As + warp * (16 * 20);
    const int bIdx = m0 >> 11;
    const int n0 = (m0 & 2047) + wy * 64;
    const int dg = d0 + wx * 64;
    const int which = dg / DIM;
    const int dbase = dg % DIM;   // multiple of 64
    __half* dstb = (which == 0) ? g_q : (which == 1) ? g_k : g_v;
    const size_t headbase0 = ((size_t)bIdx * NHEAD) * SEQ;
    const int row = lane >> 1, c0 = (lane & 1) << 3;

#pragma unroll
    for (int ms = 0; ms < 4; ms++)
#pragma unroll
        for (int ns = 0; ns < 4; ns++) {
            wmma::store_matrix_sync(Ep, acc[ms][ns], 20, wmma::mem_row_major);
            __syncwarp();
            const float* src = &Ep[row * 20 + c0];
            __half tmp[8];
#pragma unroll
            for (int j = 0; j < 8; j++) tmp[j] = __float2half_rn(src[j]);
            int dl = dbase + ns * 16;
            int h = dl >> 6;
            int hd = (dl & 63) + c0;
            size_t off = (headbase0 + (size_t)h * SEQ + n0 + ms * 16 + row) * HDIM + hd;
            *(uint4*)&dstb[off] = *(uint4*)tmp;
            __syncwarp();
        }
}

// ---------------------------------------------------------------------------
// Kernel 2: flash attention (fp16 wmma) over compacted keys.
// 128 query rows/block (256 thr, 8 warps), 64-row KV tiles, Q fragments
// preloaded, K+V register-prefetched gathers, 2 block barriers per tile.
// ---------------------------------------------------------------------------
#define SF_OFF 0                            // float [128][68]   34816 B
#define QS_OFF 34816                        // half  [128][72]   18432 B
#define EH_OFF (QS_OFF + 18432)             // half  [128][72]   18432 B
#define KS_OFF (EH_OFF + 18432)             // half  [64][72]     9216 B
#define VS_OFF (KS_OFF + 9216)              // half  [64][72]     9216 B
#define LS_OFF (VS_OFF + 9216)              // float [128]         512 B
#define MV_OFF (LS_OFF + 512)               // float [64]          256 B
#define ATTN_SMEM_B (MV_OFF + 256)          // 90880 B

__global__ __launch_bounds__(256, 2) void attn_kernel()
{
    extern __shared__ char dyn[];
    float*  Sf = (float*)(dyn + SF_OFF);
    __half* Qs = (__half*)(dyn + QS_OFF);
    __half* Eh = (__half*)(dyn + EH_OFF);
    __half* Ks = (__half*)(dyn + KS_OFF);
    __half* Vs = (__half*)(dyn + VS_OFF);
    float*  lsum = (float*)(dyn + LS_OFF);
    float*  meanv = (float*)(dyn + MV_OFF);

    const int tid = threadIdx.x;
    const int warp = tid >> 5;
    const int bh = blockIdx.y;
    const int b = bh / NHEAD, h = bh % NHEAD;
    const int q0 = blockIdx.x * 128;
    const __half* qb = g_q + (size_t)bh * SEQ * HDIM;
    const __half* kb = g_k + (size_t)bh * SEQ * HDIM;
    const __half* vb = g_v + (size_t)bh * SEQ * HDIM;
    const int cnt = g_cnt[b];
    const int* idxb = g_idx + b * SEQ;

    if (cnt == 0) {
        // All keys masked: softmax uniform -> output = mean of V rows.
        if (tid < 64) {
            float acc = 0.f;
            for (int k = 0; k < SEQ; k++) acc += __half2float(vb[(size_t)k * HDIM + tid]);
            meanv[tid] = acc / (float)SEQ;
        }
        __syncthreads();
        int row = tid >> 1, half32 = (tid & 1) * 32;
        __half* dst = g_x + (size_t)(b * SEQ + q0 + row) * DIM + h * HDIM + half32;
#pragma unroll
        for (int c = 0; c < 32; c++) dst[c] = __float2half_rn(meanv[half32 + c]);
        return;
    }

    // Load Q tile (128 x 64 halves) into Qs
#pragma unroll
    for (int i = 0; i < 4; i++) {
        int idx = tid + 256 * i;          // 0..1023 8-half chunks
        int r = idx >> 3, c8 = (idx & 7) << 3;
        *(uint4*)&Qs[r * 72 + c8] = *(const uint4*)&qb[(size_t)(q0 + r) * HDIM + c8];
    }
    if (tid < 128) lsum[tid] = 0.f;
    __syncthreads();

    // Preload Q fragments for this warp's 16-row strip (reused all tiles)
    HA aq[4];
#pragma unroll
    for (int ks = 0; ks < 4; ks++)
        wmma::load_matrix_sync(aq[ks], &Qs[(warp * 16) * 72 + ks * 16], 72);

    HC ofrag[4];
#pragma unroll
    for (int dn = 0; dn < 4; dn++) wmma::fill_fragment(ofrag[dn], 0.f);

    const int ntiles = (cnt + 63) >> 6;

    // Prologue: gather indices + K/V tile 0 (64 rows x 64 halves)
    int src[2];
    uint4 kreg[2], vreg[2];
#pragma unroll
    for (int i = 0; i < 2; i++) {
        int idx = tid + 256 * i;
        int r = idx >> 3;
        src[i] = (r < cnt) ? __ldg(&idxb[r]) : 0;
        int c8 = (idx & 7) << 3;
        kreg[i] = *(const uint4*)&kb[(size_t)src[i] * HDIM + c8];
        vreg[i] = *(const uint4*)&vb[(size_t)src[i] * HDIM + c8];
    }

    for (int tile = 0; tile < ntiles; tile++) {
        const int k0 = tile << 6;
        __syncthreads(); // prev-tile PV reads of Vs/Eh done

#pragma unroll
        for (int i = 0; i < 2; i++) {
            int idx = tid + 256 * i;
            int r = idx >> 3, c8 = (idx & 7) << 3;
            *(uint4*)&Ks[r * 72 + c8] = kreg[i];
            *(uint4*)&Vs[r * 72 + c8] = vreg[i];
        }
        __syncthreads(); // K/V visible

        // Prefetch next-tile gathers — overlaps S + exp + PV
        if (tile + 1 < ntiles) {
            const int kn = k0 + 64;
#pragma unroll
            for (int i = 0; i < 2; i++) {
                int idx = tid + 256 * i;
                int r = idx >> 3;
                int g = kn + r;
                src[i] = (g < cnt) ? __ldg(&idxb[g]) : 0;
                int c8 = (idx & 7) << 3;
                kreg[i] = *(const uint4*)&kb[(size_t)src[i] * HDIM + c8];
                vreg[i] = *(const uint4*)&vb[(size_t)src[i] * HDIM + c8];
            }
        }

        // S = Q K^T for this warp's 16-row strip (16 x 64)
        HC sfrag[4];
#pragma unroll
        for (int jn = 0; jn < 4; jn++) wmma::fill_fragment(sfrag[jn], 0.f);
#pragma unroll
        for (int ks = 0; ks < 4; ks++) {
#pragma unroll
            for (int jn = 0; jn < 4; jn++) {
                HBc bk;
                wmma::load_matrix_sync(bk, &Ks[(jn * 16) * 72 + ks * 16], 72);
                wmma::mma_sync(sfrag[jn], aq[ks], bk, sfrag[jn]);
            }
        }
#pragma unroll
        for (int jn = 0; jn < 4; jn++)
            wmma::store_matrix_sync(&Sf[(warp * 16) * 68 + jn * 16], sfrag[jn], 68,
                                    wmma::mem_row_major);
        __syncwarp(); // S strip is warp-local

        // exp (+ mask tail), convert to fp16 E, row-sum accumulate.
        {
            const int row = tid >> 1, half32 = (tid & 1) * 32;
            const int valid = cnt - k0;
            const float* sr = &Sf[row * 68 + half32];
            __half* er = &Eh[row * 72 + half32];
            float ps = 0.f;
#pragma unroll
            for (int c4 = 0; c4 < 32; c4 += 4) {
                float4 v = *(const float4*)&sr[c4];
                int jb = half32 + c4;
                v.x = (jb + 0 < valid) ? __expf(v.x * SCALE) : 0.f;
                v.y = (jb + 1 < valid) ? __expf(v.y * SCALE) : 0.f;
                v.z = (jb + 2 < valid) ? __expf(v.z * SCALE) : 0.f;
                v.w = (jb + 3 < valid) ? __expf(v.w * SCALE) : 0.f;
                ps += v.x + v.y + v.z + v.w;
                __half2 e0 = __floats2half2_rn(v.x, v.y);
                __half2 e1 = __floats2half2_rn(v.z, v.w);
                uint2 u; u.x = *(uint32_t*)&e0; u.y = *(uint32_t*)&e1;
                *(uint2*)&er[c4] = u;
            }
            ps += __shfl_xor_sync(0xffffffffu, ps, 1);
            if ((tid & 1) == 0) lsum[row] += ps;
        }
        __syncwarp(); // E updates warp-local

        // O += E V  (E 16x64 per warp, V 64x64)
#pragma unroll
        for (int js = 0; js < 4; js++) {
            HA ap;
            wmma::load_matrix_sync(ap, &Eh[(warp * 16) * 72 + js * 16], 72);
#pragma unroll
            for (int dn = 0; dn < 4; dn++) {
                HBr bv;
                wmma::load_matrix_sync(bv, &Vs[(js * 16) * 72 + dn * 16], 72);
                wmma::mma_sync(ofrag[dn], ap, bv, ofrag[dn]);
            }
        }
    }

    // Final: normalize, convert to fp16, write g_x (warp-local staging).
#pragma unroll
    for (int dn = 0; dn < 4; dn++)
        wmma::store_matrix_sync(&Sf[(warp * 16) * 68 + dn * 16], ofrag[dn], 68,
                                wmma::mem_row_major);
    __syncwarp();
    {
        const int row = tid >> 1, half32 = (tid & 1) * 32;
        const float inv = 1.f / lsum[row];
        const float* srcp = &Sf[row * 68 + half32];
        __half* dst = g_x + (size_t)(b * SEQ + q0 + row) * DIM + h * HDIM + half32;
        __half tmp[32];
#pragma unroll
        for (int c = 0; c < 32; c++) tmp[c] = __float2half_rn(srcp[c] * inv);
#pragma unroll
        for (int c = 0; c < 4; c++)
            *(uint4*)&dst[c * 8] = *(uint4*)&tmp[c * 8];
    }
}

// ---------------------------------------------------------------------------
// Kernel 3: FC projection (fp16 wmma). out[m,d] = sum_c x[m,c]*W[d,c] + b[d].
// 128x64 block tile, 4 warps (2x2), warp tile 64x32.
// ---------------------------------------------------------------------------
__global__ __launch_bounds__(128, 3) void fc_kernel(
    const float* __restrict__ bias, float* __restrict__ out)
{
    __shared__ __half As[128 * LDH];
    __shared__ __half Ws[64 * LDH];

    const int tid = threadIdx.x;
    const int warp = tid >> 5;
    const int lane = tid & 31;
    const int wy = warp >> 1;
    const int wx = warp & 1;
    const int m0 = blockIdx.y << 7;
    const int d0 = blockIdx.x << 6;

    HC acc[4][2];
#pragma unroll
    for (int i = 0; i < 4; i++)
#pragma unroll
        for (int j = 0; j < 2; j++) wmma::fill_fragment(acc[i][j], 0.f);

    const int ar = tid >> 2;
    const int ac8 = (tid & 3) << 3;

    uint4 pa[4], pw[2];
#pragma unroll
    for (int i = 0; i < 4; i++)
        pa[i] = *(const uint4*)&g_x[(size_t)(m0 + ar + 32 * i) * DIM + ac8];
#pragma unroll
    for (int i = 0; i < 2; i++)
        pw[i] = *(const uint4*)&g_wf[(size_t)(d0 + ar + 32 * i) * DIM + ac8];

    for (int c = 0; c < NCHUNK; c++) {
#pragma unroll
        for (int i = 0; i < 4; i++)
            *(uint4*)&As[(ar + 32 * i) * LDH + ac8] = pa[i];
#pragma unroll
        for (int i = 0; i < 2; i++)
            *(uint4*)&Ws[(ar + 32 * i) * LDH + ac8] = pw[i];
        __syncthreads();
        if (c + 1 < NCHUNK) {
            const int kc = (c + 1) * BK;
#pragma unroll
            for (int i = 0; i < 4; i++)
                pa[i] = *(const uint4*)&g_x[(size_t)(m0 + ar + 32 * i) * DIM + kc + ac8];
#pragma unroll
            for (int i = 0; i < 2; i++)
                pw[i] = *(const uint4*)&g_wf[(size_t)(d0 + ar + 32 * i) * DIM + kc + ac8];
        }
#pragma unroll
        for (int ks = 0; ks < 2; ks++) {
            HA am[4];
            HBc bn[2];
#pragma unroll
            for (int ms = 0; ms < 4; ms++)
                wmma::load_matrix_sync(am[ms], &As[(wy * 64 + ms * 16) * LDH + ks * 16], LDH);
#pragma unroll
            for (int ns = 0; ns < 2; ns++)
                wmma::load_matrix_sync(bn[ns], &Ws[(wx * 32 + ns * 16) * LDH + ks * 16], LDH);
#pragma unroll
            for (int ms = 0; ms < 4; ms++)
#pragma unroll
                for (int ns = 0; ns < 2; ns++)
                    wmma::mma_sync(acc[ms][ns], am[ms], bn[ns], acc[ms][ns]);
        }
        __syncthreads();
    }

    // Epilogue: per-warp smem staging (reuse As), add bias, store float.
    float* Ep = (float*)As + warp * (16 * 20);
    const int row = lane >> 1, c0 = (lane & 1) << 3;
#pragma unroll
    for (int ms = 0; ms < 4; ms++)
#pragma unroll
        for (int ns = 0; ns < 2; ns++) {
            wmma::store_matrix_sync(Ep, acc[ms][ns], 20, wmma::mem_row_major);
            __syncwarp();
            const float* src = &Ep[row * 20 + c0];
            int d = d0 + wx * 32 + ns * 16 + c0;
            float4 v0 = *(const float4*)&src[0];
            float4 v1 = *(const float4*)&src[4];
            float4 b0 = *(const float4*)&bias[d];
            float4 b1 = *(const float4*)&bias[d + 4];
            v0.x += b0.x; v0.y += b0.y; v0.z += b0.z; v0.w += b0.w;
            v1.x += b1.x; v1.y += b1.y; v1.z += b1.z; v1.w += b1.w;
            float* op = &out[(size_t)(m0 + wy * 64 + ms * 16 + row) * DIM + d];
            *(float4*)&op[0] = v0;
            *(float4*)&op[4] = v1;
            __syncwarp();
        }
}

// ---------------------------------------------------------------------------
// Launch
// ---------------------------------------------------------------------------
extern "C" void kernel_launch(void* const* d_in, const int* in_sizes, int n_in,
                              void* d_out, int out_size)
{
    const float* inputs = (const float*)d_in[0];
    const int*   pmask  = (const int*)d_in[1];
    const float* w_qkv  = (const float*)d_in[2];
    const float* w_fc   = (const float*)d_in[3];
    const float* b_fc   = (const float*)d_in[4];
    float* out = (float*)d_out;

    __half* da;  cudaGetSymbolAddress((void**)&da, g_a);
    __half* dwq; cudaGetSymbolAddress((void**)&dwq, g_wq);
    __half* dwf; cudaGetSymbolAddress((void**)&dwf, g_wf);

    cudaFuncSetAttribute(attn_kernel,
                         cudaFuncAttributeMaxDynamicSharedMemorySize, ATTN_SMEM_B);

    compact_kernel<<<BATCH, 256>>>(pmask);
    {
        int n8 = M_TOTAL * DIM / 8;
        convert_kernel<<<(n8 + 255) / 256, 256>>>(inputs, da, n8);
        n8 = QKV_DIM * DIM / 8;
        convert_kernel<<<(n8 + 255) / 256, 256>>>(w_qkv, dwq, n8);
        n8 = DIM * DIM / 8;
        convert_kernel<<<(n8 + 255) / 256, 256>>>(w_fc, dwf, n8);
    }
    {
        dim3 grid(QKV_DIM / 128, M_TOTAL / 128); // (18, 32) = 576 CTAs
        qkv_kernel<<<grid, 128>>>();
    }
    {
        dim3 grid(SEQ / 128, BATCH * NHEAD);     // (16, 24) = 384 CTAs
        attn_kernel<<<grid, 256, ATTN_SMEM_B>>>();
    }
    {
        dim3 grid(DIM / 64, M_TOTAL / 128);      // (12, 32) = 384 CTAs
        fc_kernel<<<grid, 128>>>(b_fc, out);
    }
}